// round 3
// baseline (speedup 1.0000x reference)
#include <cuda_runtime.h>
#include <math.h>

#define Dd 768
#define Mq 8
#define Bb 16
#define Ss 2048
#define SPLITS 32
#define CHUNK 64
#define NT1 192
#define KC 192
#define MAXKS 36

#define INV_SQRT_D 0.036084391824351615f

// ---------------- scratch (device globals; no allocation) ----------------
__device__ float g_pm  [Bb][SPLITS][Mq][Dd];   // partial merged (unnormalized)
__device__ float g_psum[Bb][SPLITS][Dd];
__device__ float g_pmax[Bb][SPLITS][Dd];
__device__ float g_pmin[Bb][SPLITS][Dd];
__device__ float g_smax[Bb][SPLITS][Mq];
__device__ float g_sden[Bb][SPLITS][Mq];
__device__ int   g_cnt [Bb][SPLITS];
__device__ float g_xa  [Bb][3*Dd];            // pooled_trad
__device__ float g_xb  [Bb][(Mq+1)*Dd];       // pooled_learn
__device__ float g_h   [Bb][Dd];              // MLP hidden
__device__ float g_gp  [MAXKS][Bb][Dd];       // gemm split-K partials

// lengths are >= 1 always. If the buffer is int64 (little-endian, values
// <= 2048) every odd 32-bit word is 0; if int32, word[1] = lengths[1] >= 1.
__device__ __forceinline__ int read_len(const int* p32, int b) {
    return (p32[1] == 0) ? p32[2 * b] : p32[b];
}

__device__ __forceinline__ float wredsum(float v) {
    v += __shfl_down_sync(0xffffffffu, v, 16);
    v += __shfl_down_sync(0xffffffffu, v, 8);
    v += __shfl_down_sync(0xffffffffu, v, 4);
    v += __shfl_down_sync(0xffffffffu, v, 2);
    v += __shfl_down_sync(0xffffffffu, v, 1);
    return v;
}

// ---------------- kernel 1: fused streaming token pass ----------------
__global__ __launch_bounds__(NT1) void k_main(
    const float* __restrict__ tokens, const int* __restrict__ lengths,
    const float* __restrict__ q, const float* __restrict__ lns, const float* __restrict__ lnb)
{
    const int bs = blockIdx.x;
    const int b  = bs >> 5;          // / SPLITS
    const int sp = bs & (SPLITS - 1);
    const int len  = read_len(lengths, b);
    const int s0   = sp * CHUNK;
    const int send = min(s0 + CHUNK, len);
    const int cnt  = send - s0;
    if (threadIdx.x == 0) g_cnt[b][sp] = cnt > 0 ? cnt : 0;
    if (cnt <= 0) return;

    const int t    = threadIdx.x;
    const int lane = t & 31;
    const int wid  = t >> 5;
    const int d0   = t * 4;

    __shared__ float wred[6][16];
    __shared__ float sh_w[Mq], sh_corr[Mq], sh_mmax[Mq], sh_mden[Mq], sh_QS[Mq], sh_QB[Mq];

    // preload q*scale for this thread's 4 columns; build QS/QB block-wide
    float4 sc = *(const float4*)(lns + d0);
    float4 bi = *(const float4*)(lnb + d0);
    float qs[Mq][4];
    #pragma unroll
    for (int m = 0; m < Mq; m++) {
        float4 qv = *(const float4*)(q + m * Dd + d0);
        qs[m][0] = qv.x * sc.x; qs[m][1] = qv.y * sc.y;
        qs[m][2] = qv.z * sc.z; qs[m][3] = qv.w * sc.w;
        float pQS = qs[m][0] + qs[m][1] + qs[m][2] + qs[m][3];
        float pQB = qv.x * bi.x + qv.y * bi.y + qv.z * bi.z + qv.w * bi.w;
        pQS = wredsum(pQS);
        pQB = wredsum(pQB);
        if (lane == 0) { wred[wid][m] = pQS; wred[wid][8 + m] = pQB; }
    }
    __syncthreads();
    if (t < Mq) {
        float a = 0.f, c = 0.f;
        #pragma unroll
        for (int w = 0; w < 6; w++) { a += wred[w][t]; c += wred[w][8 + t]; }
        sh_QS[t] = a;
        sh_QB[t] = c * INV_SQRT_D;
        sh_mmax[t] = -INFINITY;
        sh_mden[t] = 0.f;
    }
    __syncthreads();

    float psum[4] = {0.f, 0.f, 0.f, 0.f};
    float pmx[4]  = {-INFINITY, -INFINITY, -INFINITY, -INFINITY};
    float pmn[4]  = { INFINITY,  INFINITY,  INFINITY,  INFINITY};
    float mg[Mq][4];
    #pragma unroll
    for (int m = 0; m < Mq; m++) { mg[m][0] = mg[m][1] = mg[m][2] = mg[m][3] = 0.f; }

    const float* xp = tokens + ((size_t)(b * (Ss + 1) + 1 + s0)) * Dd + d0;
    float4 nxt = *(const float4*)xp;

    for (int s = s0; s < send; ++s) {
        float4 x = nxt;
        xp += Dd;
        if (s + 1 < send) nxt = *(const float4*)xp;

        // pooling
        psum[0] += x.x; psum[1] += x.y; psum[2] += x.z; psum[3] += x.w;
        pmx[0] = fmaxf(pmx[0], x.x); pmx[1] = fmaxf(pmx[1], x.y);
        pmx[2] = fmaxf(pmx[2], x.z); pmx[3] = fmaxf(pmx[3], x.w);
        pmn[0] = fminf(pmn[0], x.x); pmn[1] = fminf(pmn[1], x.y);
        pmn[2] = fminf(pmn[2], x.z); pmn[3] = fminf(pmn[3], x.w);

        // per-thread partials: sum, sumsq, 8 dots
        float ps = x.x + x.y + x.z + x.w;
        float pq = x.x * x.x + x.y * x.y + x.z * x.z + x.w * x.w;
        float pd[Mq];
        #pragma unroll
        for (int m = 0; m < Mq; m++) {
            pd[m] = qs[m][0] * x.x + qs[m][1] * x.y + qs[m][2] * x.z + qs[m][3] * x.w;
        }
        ps = wredsum(ps);
        pq = wredsum(pq);
        #pragma unroll
        for (int m = 0; m < Mq; m++) pd[m] = wredsum(pd[m]);
        if (lane == 0) {
            wred[wid][0] = ps; wred[wid][1] = pq;
            #pragma unroll
            for (int m = 0; m < Mq; m++) wred[wid][2 + m] = pd[m];
        }
        __syncthreads();
        if (t < Mq) {
            float ts = 0.f, tq = 0.f, td = 0.f;
            #pragma unroll
            for (int w = 0; w < 6; w++) { ts += wred[w][0]; tq += wred[w][1]; td += wred[w][2 + t]; }
            float mu  = ts * (1.f / Dd);
            float var = fmaf(-mu, mu, tq * (1.f / Dd));
            float r   = rsqrtf(var + 1e-5f);
            float score = fmaf(r * INV_SQRT_D, fmaf(-mu, sh_QS[t], td), sh_QB[t]);
            float om = sh_mmax[t];
            float nm = fmaxf(om, score);
            float corr = (om == -INFINITY) ? 0.f : __expf(om - nm);
            float w    = __expf(score - nm);
            sh_mden[t] = fmaf(sh_mden[t], corr, w);
            sh_mmax[t] = nm;
            sh_w[t] = w; sh_corr[t] = corr;
        }
        __syncthreads();
        #pragma unroll
        for (int m = 0; m < Mq; m++) {
            float c = sh_corr[m], w = sh_w[m];
            if (c != 1.f) { mg[m][0] *= c; mg[m][1] *= c; mg[m][2] *= c; mg[m][3] *= c; }
            mg[m][0] = fmaf(w, x.x, mg[m][0]);
            mg[m][1] = fmaf(w, x.y, mg[m][1]);
            mg[m][2] = fmaf(w, x.z, mg[m][2]);
            mg[m][3] = fmaf(w, x.w, mg[m][3]);
        }
    }

    // write partials
    *(float4*)&g_psum[b][sp][d0] = make_float4(psum[0], psum[1], psum[2], psum[3]);
    *(float4*)&g_pmax[b][sp][d0] = make_float4(pmx[0], pmx[1], pmx[2], pmx[3]);
    *(float4*)&g_pmin[b][sp][d0] = make_float4(pmn[0], pmn[1], pmn[2], pmn[3]);
    #pragma unroll
    for (int m = 0; m < Mq; m++)
        *(float4*)&g_pm[b][sp][m][d0] = make_float4(mg[m][0], mg[m][1], mg[m][2], mg[m][3]);
    if (t < Mq) { g_smax[b][sp][t] = sh_mmax[t]; g_sden[b][sp][t] = sh_mden[t]; }
}

// ---------------- kernel 2: combine partials, build pooled vectors ----------------
__global__ __launch_bounds__(NT1) void k_combine(
    const float* __restrict__ tokens, const int* __restrict__ lengths)
{
    const int b = blockIdx.x;
    const int t = threadIdx.x;
    const int d0 = t * 4;

    __shared__ int   sh_cnt[SPLITS];
    __shared__ float sh_f[SPLITS][Mq];
    __shared__ float sh_inv[Mq];

    if (t < SPLITS) sh_cnt[t] = g_cnt[b][t];
    __syncthreads();
    if (t < Mq) {
        float gm = -INFINITY;
        for (int sp = 0; sp < SPLITS; sp++)
            if (sh_cnt[sp] > 0) gm = fmaxf(gm, g_smax[b][sp][t]);
        float gd = 0.f;
        for (int sp = 0; sp < SPLITS; sp++) {
            if (sh_cnt[sp] > 0) {
                float f = __expf(g_smax[b][sp][t] - gm);
                sh_f[sp][t] = f;
                gd = fmaf(g_sden[b][sp][t], f, gd);
            } else sh_f[sp][t] = 0.f;
        }
        sh_inv[t] = (gd > 0.f) ? (1.f / gd) : 0.f;
    }
    __syncthreads();

    // pooling combine
    float4 s  = make_float4(0.f, 0.f, 0.f, 0.f);
    float4 mx = make_float4(-INFINITY, -INFINITY, -INFINITY, -INFINITY);
    float4 mn = make_float4( INFINITY,  INFINITY,  INFINITY,  INFINITY);
    for (int sp = 0; sp < SPLITS; sp++) {
        if (sh_cnt[sp] <= 0) continue;
        float4 v = *(const float4*)&g_psum[b][sp][d0];
        s.x += v.x; s.y += v.y; s.z += v.z; s.w += v.w;
        v = *(const float4*)&g_pmax[b][sp][d0];
        mx.x = fmaxf(mx.x, v.x); mx.y = fmaxf(mx.y, v.y);
        mx.z = fmaxf(mx.z, v.z); mx.w = fmaxf(mx.w, v.w);
        v = *(const float4*)&g_pmin[b][sp][d0];
        mn.x = fminf(mn.x, v.x); mn.y = fminf(mn.y, v.y);
        mn.z = fminf(mn.z, v.z); mn.w = fminf(mn.w, v.w);
    }
    float invlen = 1.f / (float)read_len(lengths, b);
    *(float4*)&g_xa[b][d0]        = make_float4(s.x * invlen, s.y * invlen, s.z * invlen, s.w * invlen);
    *(float4*)&g_xa[b][Dd + d0]   = mx;
    *(float4*)&g_xa[b][2*Dd + d0] = mn;

    // merged combine -> pooled_learn
    #pragma unroll
    for (int m = 0; m < Mq; m++) {
        float4 a = make_float4(0.f, 0.f, 0.f, 0.f);
        for (int sp = 0; sp < SPLITS; sp++) {
            if (sh_cnt[sp] <= 0) continue;
            float f = sh_f[sp][m];
            float4 v = *(const float4*)&g_pm[b][sp][m][d0];
            a.x = fmaf(f, v.x, a.x); a.y = fmaf(f, v.y, a.y);
            a.z = fmaf(f, v.z, a.z); a.w = fmaf(f, v.w, a.w);
        }
        float iv = sh_inv[m];
        *(float4*)&g_xb[b][m*Dd + d0] = make_float4(a.x * iv, a.y * iv, a.z * iv, a.w * iv);
    }
    // clf token
    *(float4*)&g_xb[b][Mq*Dd + d0] = *(const float4*)(tokens + (size_t)b * (Ss + 1) * Dd + d0);
}

// ---------------- GEMM stage A: split-K partials ----------------
// C_partial[ks][b][j] = sum_{k in chunk} A[b,k] * W[k,j]
__global__ __launch_bounds__(256) void k_gemmA(int asel, int lda, const float* __restrict__ W)
{
    const float* A = (asel == 0) ? &g_xa[0][0] : (asel == 1) ? &g_xb[0][0] : &g_h[0][0];
    __shared__ float sA[16 * KC];
    const int j  = blockIdx.x * 256 + threadIdx.x;
    const int k0 = blockIdx.y * KC;

    for (int i = threadIdx.x; i < 16 * KC; i += 256) {
        int bb = i / KC;
        int kk = i - bb * KC;
        sA[i] = A[bb * lda + k0 + kk];
    }
    __syncthreads();

    float acc[16];
    #pragma unroll
    for (int bb = 0; bb < 16; bb++) acc[bb] = 0.f;

    const float* Wp = W + (size_t)k0 * Dd + j;
    for (int kk = 0; kk < KC; kk += 4) {
        float w0 = Wp[0], w1 = Wp[Dd], w2 = Wp[2*Dd], w3 = Wp[3*Dd];
        Wp += 4 * Dd;
        #pragma unroll
        for (int bb = 0; bb < 16; bb++) {
            float4 a = *(const float4*)&sA[bb * KC + kk];
            float v = acc[bb];
            v = fmaf(a.x, w0, v);
            v = fmaf(a.y, w1, v);
            v = fmaf(a.z, w2, v);
            v = fmaf(a.w, w3, v);
            acc[bb] = v;
        }
    }
    float* Pp = &g_gp[blockIdx.y][0][0] + j;
    #pragma unroll
    for (int bb = 0; bb < 16; bb++) Pp[bb * Dd] = acc[bb];
}

// ---------------- GEMM stage B: reduce + bias (+ exact gelu) ----------------
__global__ __launch_bounds__(256) void k_gemmB(
    const float* __restrict__ bias, float* __restrict__ cout_or_null,
    int ksplits, int do_gelu, int ostride, int ooff)
{
    float* Cout = cout_or_null ? cout_or_null : &g_h[0][0];
    const int idx = blockIdx.x * 256 + threadIdx.x;   // 16*768 = 12288 total
    const int bb = idx / Dd;
    const int j  = idx - bb * Dd;
    float v = bias[j];
    for (int ks = 0; ks < ksplits; ks++) v += g_gp[ks][bb][j];
    if (do_gelu) v = 0.5f * v * (1.f + erff(v * 0.70710678118654752f));
    Cout[(size_t)bb * ostride + ooff + j] = v;
}

// ---------------- launch ----------------
extern "C" void kernel_launch(void* const* d_in, const int* in_sizes, int n_in,
                              void* d_out, int out_size)
{
    const float* tokens  = (const float*)d_in[0];
    const int*   lengths = (const int*)d_in[1];   // robust int32/int64 read in-kernel
    const float* q       = (const float*)d_in[2];
    const float* lns     = (const float*)d_in[3];
    const float* lnb     = (const float*)d_in[4];
    const float* w1a     = (const float*)d_in[5];
    const float* b1a     = (const float*)d_in[6];
    const float* w2a     = (const float*)d_in[7];
    const float* b2a     = (const float*)d_in[8];
    const float* w1b     = (const float*)d_in[9];
    const float* b1b     = (const float*)d_in[10];
    const float* w2b     = (const float*)d_in[11];
    const float* b2b     = (const float*)d_in[12];
    float* out = (float*)d_out;

    k_main<<<Bb * SPLITS, NT1>>>(tokens, lengths, q, lns, lnb);
    k_combine<<<Bb, NT1>>>(tokens, lengths);

    // branch A: out_fixed = MLP(pooled_trad; w1a,b1a,w2a,b2a) -> out[:, 0:768]
    k_gemmA<<<dim3(3, 12), 256>>>(0, 3 * Dd, w1a);               // K=2304
    k_gemmB<<<48, 256>>>(b1a, nullptr, 12, 1, Dd, 0);
    k_gemmA<<<dim3(3, 4), 256>>>(2, Dd, w2a);                    // K=768
    k_gemmB<<<48, 256>>>(b2a, out, 4, 0, 2 * Dd, 0);

    // branch B: out_learn = MLP(pooled_learn; w1b,b1b,w2b,b2b) -> out[:, 768:1536]
    k_gemmA<<<dim3(3, 36), 256>>>(1, 9 * Dd, w1b);               // K=6912
    k_gemmB<<<48, 256>>>(b1b, nullptr, 36, 1, Dd, 0);
    k_gemmA<<<dim3(3, 4), 256>>>(2, Dd, w2b);                    // K=768
    k_gemmB<<<48, 256>>>(b2b, out, 4, 0, 2 * Dd, Dd);
}

// round 4
// speedup vs baseline: 1.3543x; 1.3543x over previous
#include <cuda_runtime.h>
#include <math.h>

#define Dd 768
#define Mq 8
#define Bb 16
#define Ss 2048
#define SPLITS 32
#define CHUNK 64
#define NT_MAIN 256
#define KC 192

#define INV_SQRT_D 0.036084391824351615f

// ---------------- scratch (device globals; no allocation) ----------------
__device__ float g_qs  [Mq][Dd];               // q * ln_scale
__device__ float g_QS  [Mq];                   // sum_d q*scale
__device__ float g_QB  [Mq];                   // (sum_d q*bias) / sqrt(D)
__device__ float g_pm  [Bb][SPLITS][Mq][Dd];   // partial merged (unnormalized)
__device__ float g_psum[Bb][SPLITS][Dd];
__device__ float g_pmax[Bb][SPLITS][Dd];
__device__ float g_pmin[Bb][SPLITS][Dd];
__device__ float g_smax[Bb][SPLITS][Mq];
__device__ float g_sden[Bb][SPLITS][Mq];
__device__ int   g_cnt [Bb][SPLITS];
__device__ float g_xa  [Bb][3*Dd];             // pooled_trad
__device__ float g_xb  [Bb][(Mq+1)*Dd];        // pooled_learn
__device__ float g_hA  [Bb][Dd];               // MLP hidden branch A
__device__ float g_hB  [Bb][Dd];               // MLP hidden branch B
__device__ float g_gpA [12][Bb][Dd];           // split-K partials branch A
__device__ float g_gpB [36][Bb][Dd];           // split-K partials branch B

// lengths >= 1 always; detect int32 vs int64 storage.
__device__ __forceinline__ int read_len(const int* p32, int b) {
    return (p32[1] == 0) ? p32[2 * b] : p32[b];
}

__device__ __forceinline__ float wredsum(float v) {
    v += __shfl_down_sync(0xffffffffu, v, 16);
    v += __shfl_down_sync(0xffffffffu, v, 8);
    v += __shfl_down_sync(0xffffffffu, v, 4);
    v += __shfl_down_sync(0xffffffffu, v, 2);
    v += __shfl_down_sync(0xffffffffu, v, 1);
    return v;
}
__device__ __forceinline__ float bflysum(float v) {
    v += __shfl_xor_sync(0xffffffffu, v, 16);
    v += __shfl_xor_sync(0xffffffffu, v, 8);
    v += __shfl_xor_sync(0xffffffffu, v, 4);
    v += __shfl_xor_sync(0xffffffffu, v, 2);
    v += __shfl_xor_sync(0xffffffffu, v, 1);
    return v;
}
__device__ __forceinline__ float bflymax(float v) {
    v = fmaxf(v, __shfl_xor_sync(0xffffffffu, v, 16));
    v = fmaxf(v, __shfl_xor_sync(0xffffffffu, v, 8));
    v = fmaxf(v, __shfl_xor_sync(0xffffffffu, v, 4));
    v = fmaxf(v, __shfl_xor_sync(0xffffffffu, v, 2));
    v = fmaxf(v, __shfl_xor_sync(0xffffffffu, v, 1));
    return v;
}

// ---------------- kernel 0: precompute qs = q*scale, QS, QB ----------------
__global__ __launch_bounds__(256) void k_prep(
    const float* __restrict__ q, const float* __restrict__ lns, const float* __restrict__ lnb)
{
    const int lane = threadIdx.x & 31;
    const int m    = threadIdx.x >> 5;   // 8 warps = 8 m
    float sQS = 0.f, sQB = 0.f;
    #pragma unroll
    for (int i = 0; i < 6; i++) {
        int d = lane * 4 + i * 128;
        float4 qv = *(const float4*)(q + m * Dd + d);
        float4 sv = *(const float4*)(lns + d);
        float4 bv = *(const float4*)(lnb + d);
        float4 qs = make_float4(qv.x*sv.x, qv.y*sv.y, qv.z*sv.z, qv.w*sv.w);
        *(float4*)&g_qs[m][d] = qs;
        sQS += qs.x + qs.y + qs.z + qs.w;
        sQB += qv.x*bv.x + qv.y*bv.y + qv.z*bv.z + qv.w*bv.w;
    }
    sQS = wredsum(sQS);
    sQB = wredsum(sQB);
    if (lane == 0) { g_QS[m] = sQS; g_QB[m] = sQB * INV_SQRT_D; }
}

// ---------------- kernel 1: fused streaming token pass (3 phases) ----------------
__global__ __launch_bounds__(NT_MAIN) void k_main(
    const float* __restrict__ tokens, const int* __restrict__ lengths)
{
    const int bs = blockIdx.x;
    const int b  = bs >> 5;
    const int sp = bs & (SPLITS - 1);
    const int len  = read_len(lengths, b);
    const int s0   = sp * CHUNK;
    const int cnt0 = min(s0 + CHUNK, len) - s0;
    if (threadIdx.x == 0) g_cnt[b][sp] = cnt0 > 0 ? cnt0 : 0;
    if (cnt0 <= 0) return;
    const int cnt = cnt0;

    extern __shared__ float smem[];
    float* sx       = smem;                  // [CHUNK][Dd]
    float* sh_sc    = smem + CHUNK * Dd;     // [CHUNK][9]  (padded)
    float* sh_w     = sh_sc + CHUNK * 9;     // [CHUNK][8]

    const int t    = threadIdx.x;
    const int lane = t & 31;
    const int w    = t >> 5;                 // 8 warps

    // ---- phase 1: scores; warp w owns tokens sl = w + 8k ----
    {
        const float* xbase = tokens + ((size_t)(b * (Ss + 1) + 1 + s0)) * Dd;
        float acc[8][Mq];
        float ps[8], pq[8];
        #pragma unroll
        for (int k = 0; k < 8; k++) {
            ps[k] = 0.f; pq[k] = 0.f;
            #pragma unroll
            for (int m = 0; m < Mq; m++) acc[k][m] = 0.f;
        }

        #pragma unroll
        for (int j = 0; j < 6; j++) {
            const int dj = lane * 4 + j * 128;
            float4 qs[Mq];
            #pragma unroll
            for (int m = 0; m < Mq; m++) qs[m] = *(const float4*)&g_qs[m][dj];

            #pragma unroll
            for (int k = 0; k < 8; k++) {
                const int sl = w + 8 * k;
                if (sl < cnt) {
                    float4 x = *(const float4*)(xbase + (size_t)sl * Dd + dj);
                    *(float4*)&sx[sl * Dd + dj] = x;
                    ps[k] += x.x + x.y + x.z + x.w;
                    pq[k] = fmaf(x.x, x.x, fmaf(x.y, x.y, fmaf(x.z, x.z, fmaf(x.w, x.w, pq[k]))));
                    #pragma unroll
                    for (int m = 0; m < Mq; m++) {
                        acc[k][m] = fmaf(qs[m].x, x.x, fmaf(qs[m].y, x.y,
                                    fmaf(qs[m].z, x.z, fmaf(qs[m].w, x.w, acc[k][m]))));
                    }
                }
            }
        }

        float QSr[Mq], QBr[Mq];
        #pragma unroll
        for (int m = 0; m < Mq; m++) { QSr[m] = g_QS[m]; QBr[m] = g_QB[m]; }

        #pragma unroll
        for (int k = 0; k < 8; k++) {
            const int sl = w + 8 * k;
            if (sl < cnt) {
                float ts = wredsum(ps[k]);
                float tq = wredsum(pq[k]);
                float td[Mq];
                #pragma unroll
                for (int m = 0; m < Mq; m++) td[m] = wredsum(acc[k][m]);
                if (lane == 0) {
                    float mu  = ts * (1.f / Dd);
                    float var = fmaf(-mu, mu, tq * (1.f / Dd));
                    float r   = rsqrtf(var + 1e-5f) * INV_SQRT_D;
                    #pragma unroll
                    for (int m = 0; m < Mq; m++)
                        sh_sc[sl * 9 + m] = fmaf(r, fmaf(-mu, QSr[m], td[m]), QBr[m]);
                }
            } else if (lane == 0) {
                #pragma unroll
                for (int m = 0; m < Mq; m++) sh_sc[sl * 9 + m] = -INFINITY;
            }
        }
    }
    __syncthreads();

    // ---- phase 2: chunk softmax per m (warp w handles m = w) ----
    {
        float sc0 = sh_sc[lane * 9 + w];
        float sc1 = sh_sc[(lane + 32) * 9 + w];
        float mx = bflymax(fmaxf(sc0, sc1));
        float e0 = (sc0 == -INFINITY) ? 0.f : __expf(sc0 - mx);
        float e1 = (sc1 == -INFINITY) ? 0.f : __expf(sc1 - mx);
        float den = bflysum(e0 + e1);
        sh_w[lane * Mq + w] = e0;
        sh_w[(lane + 32) * Mq + w] = e1;
        if (lane == 0) { g_smax[b][sp][w] = mx; g_sden[b][sp][w] = den; }
    }
    __syncthreads();

    // ---- phase 3: pooling + weighted merge from smem (threads 0..191) ----
    if (t < Dd / 4) {
        const int d0 = t * 4;
        float4 s4  = make_float4(0.f, 0.f, 0.f, 0.f);
        float4 mx4 = make_float4(-INFINITY, -INFINITY, -INFINITY, -INFINITY);
        float4 mn4 = make_float4( INFINITY,  INFINITY,  INFINITY,  INFINITY);
        float4 mg[Mq];
        #pragma unroll
        for (int m = 0; m < Mq; m++) mg[m] = make_float4(0.f, 0.f, 0.f, 0.f);

        for (int s = 0; s < cnt; s++) {
            float4 w0 = *(const float4*)&sh_w[s * Mq];
            float4 w1 = *(const float4*)&sh_w[s * Mq + 4];
            float4 x  = *(const float4*)&sx[s * Dd + d0];
            s4.x += x.x; s4.y += x.y; s4.z += x.z; s4.w += x.w;
            mx4.x = fmaxf(mx4.x, x.x); mx4.y = fmaxf(mx4.y, x.y);
            mx4.z = fmaxf(mx4.z, x.z); mx4.w = fmaxf(mx4.w, x.w);
            mn4.x = fminf(mn4.x, x.x); mn4.y = fminf(mn4.y, x.y);
            mn4.z = fminf(mn4.z, x.z); mn4.w = fminf(mn4.w, x.w);
            float wm[Mq] = {w0.x, w0.y, w0.z, w0.w, w1.x, w1.y, w1.z, w1.w};
            #pragma unroll
            for (int m = 0; m < Mq; m++) {
                mg[m].x = fmaf(wm[m], x.x, mg[m].x);
                mg[m].y = fmaf(wm[m], x.y, mg[m].y);
                mg[m].z = fmaf(wm[m], x.z, mg[m].z);
                mg[m].w = fmaf(wm[m], x.w, mg[m].w);
            }
        }
        *(float4*)&g_psum[b][sp][d0] = s4;
        *(float4*)&g_pmax[b][sp][d0] = mx4;
        *(float4*)&g_pmin[b][sp][d0] = mn4;
        #pragma unroll
        for (int m = 0; m < Mq; m++)
            *(float4*)&g_pm[b][sp][m][d0] = mg[m];
    }
}

// ---------------- kernel 2: combine partials, build pooled vectors ----------------
__global__ __launch_bounds__(192) void k_combine(
    const float* __restrict__ tokens, const int* __restrict__ lengths)
{
    const int b = blockIdx.x;
    const int t = threadIdx.x;
    const int d0 = t * 4;

    __shared__ int   sh_cnt[SPLITS];
    __shared__ float sh_f[SPLITS][Mq];
    __shared__ float sh_inv[Mq];

    if (t < SPLITS) sh_cnt[t] = g_cnt[b][t];
    __syncthreads();
    if (t < Mq) {
        float gm = -INFINITY;
        for (int sp = 0; sp < SPLITS; sp++)
            if (sh_cnt[sp] > 0) gm = fmaxf(gm, g_smax[b][sp][t]);
        float gd = 0.f;
        for (int sp = 0; sp < SPLITS; sp++) {
            if (sh_cnt[sp] > 0) {
                float f = __expf(g_smax[b][sp][t] - gm);
                sh_f[sp][t] = f;
                gd = fmaf(g_sden[b][sp][t], f, gd);
            } else sh_f[sp][t] = 0.f;
        }
        sh_inv[t] = (gd > 0.f) ? (1.f / gd) : 0.f;
    }
    __syncthreads();

    float4 s  = make_float4(0.f, 0.f, 0.f, 0.f);
    float4 mx = make_float4(-INFINITY, -INFINITY, -INFINITY, -INFINITY);
    float4 mn = make_float4( INFINITY,  INFINITY,  INFINITY,  INFINITY);
    for (int sp = 0; sp < SPLITS; sp++) {
        if (sh_cnt[sp] <= 0) continue;
        float4 v = *(const float4*)&g_psum[b][sp][d0];
        s.x += v.x; s.y += v.y; s.z += v.z; s.w += v.w;
        v = *(const float4*)&g_pmax[b][sp][d0];
        mx.x = fmaxf(mx.x, v.x); mx.y = fmaxf(mx.y, v.y);
        mx.z = fmaxf(mx.z, v.z); mx.w = fmaxf(mx.w, v.w);
        v = *(const float4*)&g_pmin[b][sp][d0];
        mn.x = fminf(mn.x, v.x); mn.y = fminf(mn.y, v.y);
        mn.z = fminf(mn.z, v.z); mn.w = fminf(mn.w, v.w);
    }
    float invlen = 1.f / (float)read_len(lengths, b);
    *(float4*)&g_xa[b][d0]        = make_float4(s.x*invlen, s.y*invlen, s.z*invlen, s.w*invlen);
    *(float4*)&g_xa[b][Dd + d0]   = mx;
    *(float4*)&g_xa[b][2*Dd + d0] = mn;

    #pragma unroll
    for (int m = 0; m < Mq; m++) {
        float4 a = make_float4(0.f, 0.f, 0.f, 0.f);
        for (int sp = 0; sp < SPLITS; sp++) {
            if (sh_cnt[sp] <= 0) continue;
            float f = sh_f[sp][m];
            float4 v = *(const float4*)&g_pm[b][sp][m][d0];
            a.x = fmaf(f, v.x, a.x); a.y = fmaf(f, v.y, a.y);
            a.z = fmaf(f, v.z, a.z); a.w = fmaf(f, v.w, a.w);
        }
        float iv = sh_inv[m];
        *(float4*)&g_xb[b][m*Dd + d0] = make_float4(a.x*iv, a.y*iv, a.z*iv, a.w*iv);
    }
    *(float4*)&g_xb[b][Mq*Dd + d0] = *(const float4*)(tokens + (size_t)b * (Ss + 1) * Dd + d0);
}

// ---------------- GEMM stage A body ----------------
__device__ __forceinline__ void gemm_body(
    const float* __restrict__ A, int lda, const float* __restrict__ W,
    float* __restrict__ P, int k0)
{
    __shared__ float sA[16 * KC];
    const int j = blockIdx.x * 256 + threadIdx.x;

    for (int i = threadIdx.x; i < 16 * KC; i += 256) {
        int bb = i / KC;
        int kk = i - bb * KC;
        sA[i] = A[bb * lda + k0 + kk];
    }
    __syncthreads();

    float acc[16];
    #pragma unroll
    for (int bb = 0; bb < 16; bb++) acc[bb] = 0.f;

    const float* Wp = W + (size_t)k0 * Dd + j;
    for (int kk = 0; kk < KC; kk += 4) {
        float w0 = Wp[0], w1 = Wp[Dd], w2 = Wp[2*Dd], w3 = Wp[3*Dd];
        Wp += 4 * Dd;
        #pragma unroll
        for (int bb = 0; bb < 16; bb++) {
            float4 a = *(const float4*)&sA[bb * KC + kk];
            float v = acc[bb];
            v = fmaf(a.x, w0, v);
            v = fmaf(a.y, w1, v);
            v = fmaf(a.z, w2, v);
            v = fmaf(a.w, w3, v);
            acc[bb] = v;
        }
    }
    #pragma unroll
    for (int bb = 0; bb < 16; bb++) P[bb * Dd + j] = acc[bb];
}

// layer-1 GEMM partials, both branches (z: 0=A K=2304/12 splits, 1=B K=6912/36 splits)
__global__ __launch_bounds__(256) void k_g1(const float* __restrict__ w1a, const float* __restrict__ w1b)
{
    const int br = blockIdx.z;
    if (br == 0 && blockIdx.y >= 12) return;
    const float* A = br ? &g_xb[0][0] : &g_xa[0][0];
    const int lda  = br ? (Mq + 1) * Dd : 3 * Dd;
    const float* W = br ? w1b : w1a;
    float* P = (br ? &g_gpB[0][0][0] : &g_gpA[0][0][0]) + (size_t)blockIdx.y * Bb * Dd;
    gemm_body(A, lda, W, P, blockIdx.y * KC);
}

// layer-1 reduce + bias + exact gelu, both branches
__global__ __launch_bounds__(256) void k_r1(const float* __restrict__ b1a, const float* __restrict__ b1b)
{
    const int br  = blockIdx.y;
    const int idx = blockIdx.x * 256 + threadIdx.x;   // 16*768
    const int bb  = idx / Dd;
    const int j   = idx - bb * Dd;
    float v;
    if (br) {
        v = b1b[j];
        #pragma unroll
        for (int ks = 0; ks < 36; ks++) v += g_gpB[ks][bb][j];
    } else {
        v = b1a[j];
        #pragma unroll
        for (int ks = 0; ks < 12; ks++) v += g_gpA[ks][bb][j];
    }
    v = 0.5f * v * (1.f + erff(v * 0.70710678118654752f));
    (br ? g_hB : g_hA)[bb][j] = v;
}

// layer-2 GEMM partials, both branches (K=768, 4 splits each)
__global__ __launch_bounds__(256) void k_g2(const float* __restrict__ w2a, const float* __restrict__ w2b)
{
    const int br = blockIdx.z;
    const float* A = br ? &g_hB[0][0] : &g_hA[0][0];
    const float* W = br ? w2b : w2a;
    float* P = (br ? &g_gpB[0][0][0] : &g_gpA[0][0][0]) + (size_t)blockIdx.y * Bb * Dd;
    gemm_body(A, Dd, W, P, blockIdx.y * KC);
}

// layer-2 reduce + bias -> output halves
__global__ __launch_bounds__(256) void k_r2(const float* __restrict__ b2a, const float* __restrict__ b2b,
                                            float* __restrict__ out)
{
    const int br  = blockIdx.y;
    const int idx = blockIdx.x * 256 + threadIdx.x;
    const int bb  = idx / Dd;
    const int j   = idx - bb * Dd;
    float v = br ? b2b[j] : b2a[j];
    if (br) {
        #pragma unroll
        for (int ks = 0; ks < 4; ks++) v += g_gpB[ks][bb][j];
    } else {
        #pragma unroll
        for (int ks = 0; ks < 4; ks++) v += g_gpA[ks][bb][j];
    }
    out[(size_t)bb * (2 * Dd) + br * Dd + j] = v;
}

// ---------------- launch ----------------
extern "C" void kernel_launch(void* const* d_in, const int* in_sizes, int n_in,
                              void* d_out, int out_size)
{
    const float* tokens  = (const float*)d_in[0];
    const int*   lengths = (const int*)d_in[1];
    const float* q       = (const float*)d_in[2];
    const float* lns     = (const float*)d_in[3];
    const float* lnb     = (const float*)d_in[4];
    const float* w1a     = (const float*)d_in[5];
    const float* b1a     = (const float*)d_in[6];
    const float* w2a     = (const float*)d_in[7];
    const float* b2a     = (const float*)d_in[8];
    const float* w1b     = (const float*)d_in[9];
    const float* b1b     = (const float*)d_in[10];
    const float* w2b     = (const float*)d_in[11];
    const float* b2b     = (const float*)d_in[12];
    float* out = (float*)d_out;

    const int smem_main = (CHUNK * Dd + CHUNK * 9 + CHUNK * Mq) * (int)sizeof(float);
    static int smem_set = 0;
    if (!smem_set) {
        cudaFuncSetAttribute(k_main, cudaFuncAttributeMaxDynamicSharedMemorySize, smem_main);
        smem_set = 1;
    }

    k_prep<<<1, 256>>>(q, lns, lnb);
    k_main<<<Bb * SPLITS, NT_MAIN, smem_main>>>(tokens, lengths);
    k_combine<<<Bb, 192>>>(tokens, lengths);

    k_g1<<<dim3(3, 36, 2), 256>>>(w1a, w1b);
    k_r1<<<dim3(48, 2), 256>>>(b1a, b1b);
    k_g2<<<dim3(3, 4, 2), 256>>>(w2a, w2b);
    k_r2<<<dim3(48, 2), 256>>>(b2a, b2b, out);
}

// round 5
// speedup vs baseline: 2.1126x; 1.5599x over previous
#include <cuda_runtime.h>
#include <math.h>

#define Dd 768
#define Mq 8
#define Bb 16
#define Ss 2048
#define SPLITS 32
#define CHUNK 64
#define NT_MAIN 256
#define KC 48
#define NS_A 48     /* 2304 / KC */
#define NS_B 144    /* 6912 / KC */
#define NS_2 16     /* 768 / KC  */

#define INV_SQRT_D 0.036084391824351615f

// ---------------- scratch (device globals; no allocation) ----------------
__device__ float g_qs  [Mq][Dd];               // q * ln_scale
__device__ float g_QS  [Mq];                   // sum_d q*scale
__device__ float g_QB  [Mq];                   // (sum_d q*bias) / sqrt(D)
__device__ float g_pm  [Bb][SPLITS][Mq][Dd];   // partial merged (unnormalized)
__device__ float g_psum[Bb][SPLITS][Dd];
__device__ float g_pmax[Bb][SPLITS][Dd];
__device__ float g_pmin[Bb][SPLITS][Dd];
__device__ float g_smax[Bb][SPLITS][Mq];
__device__ float g_sden[Bb][SPLITS][Mq];
__device__ int   g_cnt [Bb][SPLITS];
__device__ float g_xa  [Bb][3*Dd];             // pooled_trad
__device__ float g_xb  [Bb][(Mq+1)*Dd];        // pooled_learn
__device__ float g_hA  [Bb][Dd];               // MLP hidden branch A
__device__ float g_hB  [Bb][Dd];               // MLP hidden branch B
__device__ float g_gpA [NS_A][Bb][Dd];         // split-K partials branch A
__device__ float g_gpB [NS_B][Bb][Dd];         // split-K partials branch B

// lengths >= 1 always; detect int32 vs int64 storage.
__device__ __forceinline__ int read_len(const int* p32, int b) {
    return (p32[1] == 0) ? p32[2 * b] : p32[b];
}

__device__ __forceinline__ float wredsum(float v) {
    v += __shfl_down_sync(0xffffffffu, v, 16);
    v += __shfl_down_sync(0xffffffffu, v, 8);
    v += __shfl_down_sync(0xffffffffu, v, 4);
    v += __shfl_down_sync(0xffffffffu, v, 2);
    v += __shfl_down_sync(0xffffffffu, v, 1);
    return v;
}
__device__ __forceinline__ float bflysum(float v) {
    v += __shfl_xor_sync(0xffffffffu, v, 16);
    v += __shfl_xor_sync(0xffffffffu, v, 8);
    v += __shfl_xor_sync(0xffffffffu, v, 4);
    v += __shfl_xor_sync(0xffffffffu, v, 2);
    v += __shfl_xor_sync(0xffffffffu, v, 1);
    return v;
}
__device__ __forceinline__ float bflymax(float v) {
    v = fmaxf(v, __shfl_xor_sync(0xffffffffu, v, 16));
    v = fmaxf(v, __shfl_xor_sync(0xffffffffu, v, 8));
    v = fmaxf(v, __shfl_xor_sync(0xffffffffu, v, 4));
    v = fmaxf(v, __shfl_xor_sync(0xffffffffu, v, 2));
    v = fmaxf(v, __shfl_xor_sync(0xffffffffu, v, 1));
    return v;
}

// ---------------- kernel 0: precompute qs = q*scale, QS, QB ----------------
__global__ __launch_bounds__(256) void k_prep(
    const float* __restrict__ q, const float* __restrict__ lns, const float* __restrict__ lnb)
{
    const int lane = threadIdx.x & 31;
    const int m    = threadIdx.x >> 5;   // 8 warps = 8 m
    float sQS = 0.f, sQB = 0.f;
    #pragma unroll
    for (int i = 0; i < 6; i++) {
        int d = lane * 4 + i * 128;
        float4 qv = *(const float4*)(q + m * Dd + d);
        float4 sv = *(const float4*)(lns + d);
        float4 bv = *(const float4*)(lnb + d);
        float4 qs = make_float4(qv.x*sv.x, qv.y*sv.y, qv.z*sv.z, qv.w*sv.w);
        *(float4*)&g_qs[m][d] = qs;
        sQS += qs.x + qs.y + qs.z + qs.w;
        sQB += qv.x*bv.x + qv.y*bv.y + qv.z*bv.z + qv.w*bv.w;
    }
    sQS = wredsum(sQS);
    sQB = wredsum(sQB);
    if (lane == 0) { g_QS[m] = sQS; g_QB[m] = sQB * INV_SQRT_D; }
}

// ---------------- phase 1 helper: scores for 8 tokens per warp ----------------
template<bool FULL>
__device__ __forceinline__ void phase1(
    const float* __restrict__ xbase, int cnt, int lane, int w, float* __restrict__ sh_sc)
{
    float acc[8][Mq];
    float ps[8], pq[8];
    #pragma unroll
    for (int k = 0; k < 8; k++) {
        ps[k] = 0.f; pq[k] = 0.f;
        #pragma unroll
        for (int m = 0; m < Mq; m++) acc[k][m] = 0.f;
    }

    #pragma unroll
    for (int j = 0; j < 6; j++) {
        const int dj = lane * 4 + j * 128;
        float4 qs[Mq];
        #pragma unroll
        for (int m = 0; m < Mq; m++) qs[m] = *(const float4*)&g_qs[m][dj];

        #pragma unroll
        for (int k = 0; k < 8; k++) {
            const int sl = w + 8 * k;
            if (FULL || sl < cnt) {
                float4 x = *(const float4*)(xbase + (size_t)sl * Dd + dj);
                ps[k] += x.x + x.y + x.z + x.w;
                pq[k] = fmaf(x.x, x.x, fmaf(x.y, x.y, fmaf(x.z, x.z, fmaf(x.w, x.w, pq[k]))));
                #pragma unroll
                for (int m = 0; m < Mq; m++) {
                    acc[k][m] = fmaf(qs[m].x, x.x, fmaf(qs[m].y, x.y,
                                fmaf(qs[m].z, x.z, fmaf(qs[m].w, x.w, acc[k][m]))));
                }
            }
        }
    }

    float QSr[Mq], QBr[Mq];
    #pragma unroll
    for (int m = 0; m < Mq; m++) { QSr[m] = g_QS[m]; QBr[m] = g_QB[m]; }

    #pragma unroll
    for (int k = 0; k < 8; k++) {
        const int sl = w + 8 * k;
        if (FULL || sl < cnt) {
            float ts = wredsum(ps[k]);
            float tq = wredsum(pq[k]);
            float td[Mq];
            #pragma unroll
            for (int m = 0; m < Mq; m++) td[m] = wredsum(acc[k][m]);
            if (lane == 0) {
                float mu  = ts * (1.f / Dd);
                float var = fmaf(-mu, mu, tq * (1.f / Dd));
                float r   = rsqrtf(var + 1e-5f) * INV_SQRT_D;
                #pragma unroll
                for (int m = 0; m < Mq; m++)
                    sh_sc[sl * 9 + m] = fmaf(r, fmaf(-mu, QSr[m], td[m]), QBr[m]);
            }
        } else if (lane == 0) {
            #pragma unroll
            for (int m = 0; m < Mq; m++) sh_sc[sl * 9 + m] = -INFINITY;
        }
    }
}

// ---------------- kernel 1: fused streaming token pass (3 phases, small smem) --------
__global__ __launch_bounds__(NT_MAIN) void k_main(
    const float* __restrict__ tokens, const int* __restrict__ lengths)
{
    const int bs = blockIdx.x;
    const int b  = bs >> 5;
    const int sp = bs & (SPLITS - 1);
    const int len  = read_len(lengths, b);
    const int s0   = sp * CHUNK;
    const int cnt0 = min(s0 + CHUNK, len) - s0;
    if (threadIdx.x == 0) g_cnt[b][sp] = cnt0 > 0 ? cnt0 : 0;
    if (cnt0 <= 0) return;
    const int cnt = cnt0;

    __shared__ float sh_sc[CHUNK * 9];
    __shared__ float sh_w [CHUNK * Mq];

    const int t    = threadIdx.x;
    const int lane = t & 31;
    const int w    = t >> 5;                 // 8 warps

    const float* xbase = tokens + ((size_t)(b * (Ss + 1) + 1 + s0)) * Dd;

    // ---- phase 1: scores (warp-per-token; no barriers inside) ----
    if (cnt == CHUNK) phase1<true >(xbase, cnt, lane, w, sh_sc);
    else              phase1<false>(xbase, cnt, lane, w, sh_sc);
    __syncthreads();

    // ---- phase 2: chunk softmax per m (warp w handles m = w) ----
    {
        float sc0 = sh_sc[lane * 9 + w];
        float sc1 = sh_sc[(lane + 32) * 9 + w];
        float mx = bflymax(fmaxf(sc0, sc1));
        float e0 = (sc0 == -INFINITY) ? 0.f : __expf(sc0 - mx);
        float e1 = (sc1 == -INFINITY) ? 0.f : __expf(sc1 - mx);
        float den = bflysum(e0 + e1);
        sh_w[lane * Mq + w] = e0;
        sh_w[(lane + 32) * Mq + w] = e1;
        if (lane == 0) { g_smax[b][sp][w] = mx; g_sden[b][sp][w] = den; }
    }
    __syncthreads();

    // ---- phase 3: pooling + weighted merge; re-read X from gmem (L2-hot) ----
    if (t < Dd / 4) {
        const int d0 = t * 4;
        float4 s4  = make_float4(0.f, 0.f, 0.f, 0.f);
        float4 mx4 = make_float4(-INFINITY, -INFINITY, -INFINITY, -INFINITY);
        float4 mn4 = make_float4( INFINITY,  INFINITY,  INFINITY,  INFINITY);
        float4 mg[Mq];
        #pragma unroll
        for (int m = 0; m < Mq; m++) mg[m] = make_float4(0.f, 0.f, 0.f, 0.f);

        #pragma unroll 4
        for (int s = 0; s < cnt; s++) {
            float4 x  = *(const float4*)(xbase + (size_t)s * Dd + d0);
            float4 w0 = *(const float4*)&sh_w[s * Mq];
            float4 w1 = *(const float4*)&sh_w[s * Mq + 4];
            s4.x += x.x; s4.y += x.y; s4.z += x.z; s4.w += x.w;
            mx4.x = fmaxf(mx4.x, x.x); mx4.y = fmaxf(mx4.y, x.y);
            mx4.z = fmaxf(mx4.z, x.z); mx4.w = fmaxf(mx4.w, x.w);
            mn4.x = fminf(mn4.x, x.x); mn4.y = fminf(mn4.y, x.y);
            mn4.z = fminf(mn4.z, x.z); mn4.w = fminf(mn4.w, x.w);
            float wm[Mq] = {w0.x, w0.y, w0.z, w0.w, w1.x, w1.y, w1.z, w1.w};
            #pragma unroll
            for (int m = 0; m < Mq; m++) {
                mg[m].x = fmaf(wm[m], x.x, mg[m].x);
                mg[m].y = fmaf(wm[m], x.y, mg[m].y);
                mg[m].z = fmaf(wm[m], x.z, mg[m].z);
                mg[m].w = fmaf(wm[m], x.w, mg[m].w);
            }
        }
        *(float4*)&g_psum[b][sp][d0] = s4;
        *(float4*)&g_pmax[b][sp][d0] = mx4;
        *(float4*)&g_pmin[b][sp][d0] = mn4;
        #pragma unroll
        for (int m = 0; m < Mq; m++)
            *(float4*)&g_pm[b][sp][m][d0] = mg[m];
    }
}

// ---------------- kernel 2: combine partials, build pooled vectors ----------------
__global__ __launch_bounds__(192) void k_combine(
    const float* __restrict__ tokens, const int* __restrict__ lengths)
{
    const int b = blockIdx.x;
    const int t = threadIdx.x;
    const int d0 = t * 4;

    __shared__ int   sh_cnt[SPLITS];
    __shared__ float sh_f[SPLITS][Mq];
    __shared__ float sh_inv[Mq];

    if (t < SPLITS) sh_cnt[t] = g_cnt[b][t];
    __syncthreads();
    if (t < Mq) {
        float gm = -INFINITY;
        for (int sp = 0; sp < SPLITS; sp++)
            if (sh_cnt[sp] > 0) gm = fmaxf(gm, g_smax[b][sp][t]);
        float gd = 0.f;
        for (int sp = 0; sp < SPLITS; sp++) {
            if (sh_cnt[sp] > 0) {
                float f = __expf(g_smax[b][sp][t] - gm);
                sh_f[sp][t] = f;
                gd = fmaf(g_sden[b][sp][t], f, gd);
            } else sh_f[sp][t] = 0.f;
        }
        sh_inv[t] = (gd > 0.f) ? (1.f / gd) : 0.f;
    }
    __syncthreads();

    float4 s  = make_float4(0.f, 0.f, 0.f, 0.f);
    float4 mx = make_float4(-INFINITY, -INFINITY, -INFINITY, -INFINITY);
    float4 mn = make_float4( INFINITY,  INFINITY,  INFINITY,  INFINITY);
    for (int sp = 0; sp < SPLITS; sp++) {
        if (sh_cnt[sp] <= 0) continue;
        float4 v = *(const float4*)&g_psum[b][sp][d0];
        s.x += v.x; s.y += v.y; s.z += v.z; s.w += v.w;
        v = *(const float4*)&g_pmax[b][sp][d0];
        mx.x = fmaxf(mx.x, v.x); mx.y = fmaxf(mx.y, v.y);
        mx.z = fmaxf(mx.z, v.z); mx.w = fmaxf(mx.w, v.w);
        v = *(const float4*)&g_pmin[b][sp][d0];
        mn.x = fminf(mn.x, v.x); mn.y = fminf(mn.y, v.y);
        mn.z = fminf(mn.z, v.z); mn.w = fminf(mn.w, v.w);
    }
    float invlen = 1.f / (float)read_len(lengths, b);
    *(float4*)&g_xa[b][d0]        = make_float4(s.x*invlen, s.y*invlen, s.z*invlen, s.w*invlen);
    *(float4*)&g_xa[b][Dd + d0]   = mx;
    *(float4*)&g_xa[b][2*Dd + d0] = mn;

    #pragma unroll
    for (int m = 0; m < Mq; m++) {
        float4 a = make_float4(0.f, 0.f, 0.f, 0.f);
        for (int sp = 0; sp < SPLITS; sp++) {
            if (sh_cnt[sp] <= 0) continue;
            float f = sh_f[sp][m];
            float4 v = *(const float4*)&g_pm[b][sp][m][d0];
            a.x = fmaf(f, v.x, a.x); a.y = fmaf(f, v.y, a.y);
            a.z = fmaf(f, v.z, a.z); a.w = fmaf(f, v.w, a.w);
        }
        float iv = sh_inv[m];
        *(float4*)&g_xb[b][m*Dd + d0] = make_float4(a.x*iv, a.y*iv, a.z*iv, a.w*iv);
    }
    *(float4*)&g_xb[b][Mq*Dd + d0] = *(const float4*)(tokens + (size_t)b * (Ss + 1) * Dd + d0);
}

// ---------------- GEMM stage A body (KC=48, unroll-8 weight loads) ----------------
__device__ __forceinline__ void gemm_body(
    const float* __restrict__ A, int lda, const float* __restrict__ W,
    float* __restrict__ P, int k0)
{
    __shared__ float sA[16 * KC];
    const int j = blockIdx.x * 256 + threadIdx.x;

    for (int i = threadIdx.x; i < 16 * KC; i += 256) {
        int bb = i / KC;
        int kk = i - bb * KC;
        sA[i] = A[bb * lda + k0 + kk];
    }
    __syncthreads();

    float acc[16];
    #pragma unroll
    for (int bb = 0; bb < 16; bb++) acc[bb] = 0.f;

    const float* Wp = W + (size_t)k0 * Dd + j;
    #pragma unroll
    for (int kk = 0; kk < KC; kk += 8) {
        float wv[8];
        #pragma unroll
        for (int u = 0; u < 8; u++) wv[u] = Wp[u * Dd];
        Wp += 8 * Dd;
        #pragma unroll
        for (int bb = 0; bb < 16; bb++) {
            float4 a0 = *(const float4*)&sA[bb * KC + kk];
            float4 a1 = *(const float4*)&sA[bb * KC + kk + 4];
            float v = acc[bb];
            v = fmaf(a0.x, wv[0], v);
            v = fmaf(a0.y, wv[1], v);
            v = fmaf(a0.z, wv[2], v);
            v = fmaf(a0.w, wv[3], v);
            v = fmaf(a1.x, wv[4], v);
            v = fmaf(a1.y, wv[5], v);
            v = fmaf(a1.z, wv[6], v);
            v = fmaf(a1.w, wv[7], v);
            acc[bb] = v;
        }
    }
    #pragma unroll
    for (int bb = 0; bb < 16; bb++) P[bb * Dd + j] = acc[bb];
}

// layer-1 GEMM partials, both branches (z: 0=A 48 splits, 1=B 144 splits)
__global__ __launch_bounds__(256) void k_g1(const float* __restrict__ w1a, const float* __restrict__ w1b)
{
    const int br = blockIdx.z;
    if (br == 0 && blockIdx.y >= NS_A) return;
    const float* A = br ? &g_xb[0][0] : &g_xa[0][0];
    const int lda  = br ? (Mq + 1) * Dd : 3 * Dd;
    const float* W = br ? w1b : w1a;
    float* P = (br ? &g_gpB[0][0][0] : &g_gpA[0][0][0]) + (size_t)blockIdx.y * Bb * Dd;
    gemm_body(A, lda, W, P, blockIdx.y * KC);
}

// layer-1 reduce + bias + exact gelu, both branches
__global__ __launch_bounds__(256) void k_r1(const float* __restrict__ b1a, const float* __restrict__ b1b)
{
    const int br  = blockIdx.y;
    const int idx = blockIdx.x * 256 + threadIdx.x;   // 16*768
    const int bb  = idx / Dd;
    const int j   = idx - bb * Dd;
    float v;
    if (br) {
        v = b1b[j];
        #pragma unroll
        for (int ks = 0; ks < NS_B; ks++) v += g_gpB[ks][bb][j];
    } else {
        v = b1a[j];
        #pragma unroll
        for (int ks = 0; ks < NS_A; ks++) v += g_gpA[ks][bb][j];
    }
    v = 0.5f * v * (1.f + erff(v * 0.70710678118654752f));
    (br ? g_hB : g_hA)[bb][j] = v;
}

// layer-2 GEMM partials, both branches (K=768, 16 splits each)
__global__ __launch_bounds__(256) void k_g2(const float* __restrict__ w2a, const float* __restrict__ w2b)
{
    const int br = blockIdx.z;
    const float* A = br ? &g_hB[0][0] : &g_hA[0][0];
    const float* W = br ? w2b : w2a;
    float* P = (br ? &g_gpB[0][0][0] : &g_gpA[0][0][0]) + (size_t)blockIdx.y * Bb * Dd;
    gemm_body(A, Dd, W, P, blockIdx.y * KC);
}

// layer-2 reduce + bias -> output halves
__global__ __launch_bounds__(256) void k_r2(const float* __restrict__ b2a, const float* __restrict__ b2b,
                                            float* __restrict__ out)
{
    const int br  = blockIdx.y;
    const int idx = blockIdx.x * 256 + threadIdx.x;
    const int bb  = idx / Dd;
    const int j   = idx - bb * Dd;
    float v = br ? b2b[j] : b2a[j];
    if (br) {
        #pragma unroll
        for (int ks = 0; ks < NS_2; ks++) v += g_gpB[ks][bb][j];
    } else {
        #pragma unroll
        for (int ks = 0; ks < NS_2; ks++) v += g_gpA[ks][bb][j];
    }
    out[(size_t)bb * (2 * Dd) + br * Dd + j] = v;
}

// ---------------- launch ----------------
extern "C" void kernel_launch(void* const* d_in, const int* in_sizes, int n_in,
                              void* d_out, int out_size)
{
    const float* tokens  = (const float*)d_in[0];
    const int*   lengths = (const int*)d_in[1];
    const float* q       = (const float*)d_in[2];
    const float* lns     = (const float*)d_in[3];
    const float* lnb     = (const float*)d_in[4];
    const float* w1a     = (const float*)d_in[5];
    const float* b1a     = (const float*)d_in[6];
    const float* w2a     = (const float*)d_in[7];
    const float* b2a     = (const float*)d_in[8];
    const float* w1b     = (const float*)d_in[9];
    const float* b1b     = (const float*)d_in[10];
    const float* w2b     = (const float*)d_in[11];
    const float* b2b     = (const float*)d_in[12];
    float* out = (float*)d_out;

    k_prep<<<1, 256>>>(q, lns, lnb);
    k_main<<<Bb * SPLITS, NT_MAIN>>>(tokens, lengths);
    k_combine<<<Bb, 192>>>(tokens, lengths);

    k_g1<<<dim3(3, NS_B, 2), 256>>>(w1a, w1b);
    k_r1<<<dim3(48, 2), 256>>>(b1a, b1b);
    k_g2<<<dim3(3, NS_2, 2), 256>>>(w2a, w2b);
    k_r2<<<dim3(48, 2), 256>>>(b2a, b2b, out);
}